// round 17
// baseline (speedup 1.0000x reference)
#include <cuda_runtime.h>
#include <cuda_fp16.h>
#include <cstdint>

#define T_TOKENS 32768
#define D_DIM    512
#define F_DIM    2048
#define N_EXP    64

#define BM 128
#define BN 128
#define BK 64
#define NTH 128

// smem geometry (bank-conflict-engineered strides)
#define A_ROW_B   144
#define B_ROW_B   272
#define A_STAGE_B (BM * A_ROW_B)          // 18432
#define B_STAGE_B (BK * B_ROW_B)          // 17408
#define STAGES    3
#define DSMEM_B   (STAGES * (A_STAGE_B + B_STAGE_B))   // 107520 -> 2 CTAs/SM

#define WELEMS    (N_EXP * D_DIM * F_DIM)              // 67,108,864
#define PAD_ROWS  128

// work queue: 9216 phase-1 items (8 gemm1 + 1 W2-conv per block of 9), then 2048 gemm2
#define N_PH1   9216
#define N_TOTAL 11264

// ---------------- device scratch ----------------
__device__ int    g_offsets[N_EXP + 1];
__device__ int    g_tok[T_TOKENS];
__device__ unsigned int g_qhead;
__device__ int    g_flag1[N_EXP];     // gemm1 completions per expert (target 128)
__device__ int    g_cflag[N_EXP];     // W2-conv completions per expert (target 16)
__device__ __half g_Xg [(size_t)(T_TOKENS + PAD_ROWS) * D_DIM];
__device__ __half g_Hh [(size_t)(T_TOKENS + PAD_ROWS) * F_DIM];
__device__ __half g_W1h[(size_t)WELEMS];
__device__ __half g_W2h[(size_t)WELEMS];

// ---------------- helpers ----------------
__device__ __forceinline__ float gelu_exact(float x) {
    return 0.5f * x * (1.0f + erff(x * 0.70710678118654752f));
}

__device__ __forceinline__ uint32_t smem_u32(const void* p) {
    uint32_t a;
    asm("{ .reg .u64 t; cvta.to.shared.u64 t, %1; cvt.u32.u64 %0, t; }" : "=r"(a) : "l"(p));
    return a;
}

__device__ __forceinline__ void cp16(uint32_t dst, const void* src) {
    asm volatile("cp.async.cg.shared.global [%0], [%1], 16;" :: "r"(dst), "l"(src));
}
#define CP_COMMIT() asm volatile("cp.async.commit_group;")

#define LDSM_X4(r, addr) \
    asm volatile("ldmatrix.sync.aligned.m8n8.x4.shared.b16 {%0,%1,%2,%3}, [%4];" \
        : "=r"((r)[0]), "=r"((r)[1]), "=r"((r)[2]), "=r"((r)[3]) : "r"(addr))

#define LDSM_X4_T(r0, r1, r2, r3, addr) \
    asm volatile("ldmatrix.sync.aligned.m8n8.x4.trans.shared.b16 {%0,%1,%2,%3}, [%4];" \
        : "=r"(r0), "=r"(r1), "=r"(r2), "=r"(r3) : "r"(addr))

__device__ __forceinline__ void mma_f16(float* c, const uint32_t* a, const uint32_t* b) {
    asm volatile(
        "mma.sync.aligned.m16n8k16.row.col.f32.f16.f16.f32 "
        "{%0,%1,%2,%3}, {%4,%5,%6,%7}, {%8,%9}, {%0,%1,%2,%3};"
        : "+f"(c[0]), "+f"(c[1]), "+f"(c[2]), "+f"(c[3])
        : "r"(a[0]), "r"(a[1]), "r"(a[2]), "r"(a[3]), "r"(b[0]), "r"(b[1]));
}

__device__ __forceinline__ uint32_t pack_h2(float lo, float hi) {
    uint32_t d;
    asm("cvt.rn.f16x2.f32 %0, %1, %2;" : "=r"(d) : "f"(hi), "f"(lo));
    return d;
}

// ---------------- prep: block 0 = dispatch + flag reset; blocks 1.. = W1 fp32->fp16 ----------------
__global__ void prep_kernel(const int* __restrict__ disp, const float* __restrict__ W1) {
    const int tid = threadIdx.x;            // 1024 threads
    if (blockIdx.x == 0) {
        __shared__ int cnt[N_EXP];
        __shared__ int off[N_EXP];
        if (tid < N_EXP) { cnt[tid] = 0; g_flag1[tid] = 0; g_cflag[tid] = 0; }
        if (tid == 0) g_qhead = 0;
        __syncthreads();
        for (int t = tid; t < T_TOKENS; t += 1024) atomicAdd(&cnt[disp[t]], 1);
        __syncthreads();
        if (tid == 0) {
            int s = 0;
            for (int e = 0; e < N_EXP; e++) { off[e] = s; g_offsets[e] = s; s += cnt[e]; }
            g_offsets[N_EXP] = s;
        }
        __syncthreads();
        if (tid < N_EXP) cnt[tid] = 0;
        __syncthreads();
        for (int t = tid; t < T_TOKENS; t += 1024) {
            int e = disp[t];
            int p = atomicAdd(&cnt[e], 1);
            g_tok[off[e] + p] = t;
        }
    } else {
        size_t i = ((size_t)(blockIdx.x - 1) * 1024 + tid) * 8;
        float4 v0 = *reinterpret_cast<const float4*>(&W1[i]);
        float4 v1 = *reinterpret_cast<const float4*>(&W1[i + 4]);
        uint4 o;
        o.x = pack_h2(v0.x, v0.y); o.y = pack_h2(v0.z, v0.w);
        o.z = pack_h2(v1.x, v1.y); o.w = pack_h2(v1.z, v1.w);
        *reinterpret_cast<uint4*>(&g_W1h[i]) = o;
    }
}

// ---------------- gather + convert X ----------------
__global__ void gather_x_kernel(const float* __restrict__ X) {
    const int slot  = blockIdx.x * 2 + (threadIdx.x >> 7);
    const int local = threadIdx.x & 127;
    const int tok   = g_tok[slot];
    float4 v = *reinterpret_cast<const float4*>(&X[(size_t)tok * D_DIM + local * 4]);
    uint2 o;
    o.x = pack_h2(v.x, v.y); o.y = pack_h2(v.z, v.w);
    *reinterpret_cast<uint2*>(&g_Xg[(size_t)slot * D_DIM + local * 4]) = o;
}

// ================= persistent fused MoE kernel =================
// 304 persistent CTAs (2/SM), 128 threads = 4 warps (2x2), warp tile 64x64, BK=64.
// Work queue: idx<9216 -> blocks of 9 = 8 gemm1 items + 1 W2-conv item;
//             idx>=9216 -> gemm2 items gated on per-expert flags.
__global__ __launch_bounds__(NTH, 2) void moe_kernel(
    const float* __restrict__ W2, const float* __restrict__ B1g,
    const float* __restrict__ B2g, float* __restrict__ out)
{
    extern __shared__ char dsm[];
    __shared__ float sbias[BN];
    __shared__ int   stoks[BM];
    __shared__ unsigned int s_idx;

    const int tid  = threadIdx.x;
    const int warp = tid >> 5, lane = tid & 31;
    const int wm   = (warp & 1) * 64;
    const int wn   = (warp >> 1) * 64;

    const uint32_t sb = smem_u32(dsm);
    uint32_t uA[STAGES], uB[STAGES];
#pragma unroll
    for (int s = 0; s < STAGES; s++) {
        uA[s] = sb + s * A_STAGE_B;
        uB[s] = sb + STAGES * A_STAGE_B + s * B_STAGE_B;
    }
    const uint32_t sa_o = (tid >> 3) * A_ROW_B + (tid & 7) * 16;
    const uint32_t sb_o = (tid >> 4) * B_ROW_B + (tid & 15) * 16;

    while (true) {
        if (tid == 0) s_idx = atomicAdd(&g_qhead, 1u);
        __syncthreads();
        const unsigned idx = s_idx;
        __syncthreads();                      // protect s_idx + smem reuse
        if (idx >= N_TOTAL) return;

        if (idx < N_PH1) {
            const unsigned b = idx / 9u;
            const unsigned r = idx - b * 9u;
            if (r == 8u) {
                // ---- W2 fp32->fp16 conversion chunk (65536 elems) ----
                const size_t base_i = (size_t)b * 65536;
#pragma unroll 4
                for (int it = 0; it < 64; it++) {
                    size_t i = base_i + (size_t)it * 1024 + tid * 8;
                    float4 v0 = *reinterpret_cast<const float4*>(&W2[i]);
                    float4 v1 = *reinterpret_cast<const float4*>(&W2[i + 4]);
                    uint4 o;
                    o.x = pack_h2(v0.x, v0.y); o.y = pack_h2(v0.z, v0.w);
                    o.z = pack_h2(v1.x, v1.y); o.w = pack_h2(v1.z, v1.w);
                    *reinterpret_cast<uint4*>(&g_W2h[i]) = o;
                }
                __threadfence();
                __syncthreads();
                if (tid == 0) atomicAdd(&g_cflag[b >> 4], 1);
            } else {
                // ---- gemm1 item: H = gelu(Xg @ W1h + b1) ----
                const int g1 = (int)(b * 8u + r);
                const int x = g1 & 15, y = (g1 >> 4) & 7, e = g1 >> 7;
                const int base = g_offsets[e];
                const int ne   = g_offsets[e + 1] - base;
                const int tm   = y * BM;
                if (tm < ne) {
                    const int n0 = x * BN;
                    sbias[tid] = B1g[e * F_DIM + n0 + tid];

                    const __half* aptr = g_Xg + ((size_t)(base + tm) + (tid >> 3)) * D_DIM + (tid & 7) * 8;
                    const __half* bptr = g_W1h + ((size_t)e * D_DIM + (tid >> 4)) * F_DIM + n0 + (tid & 15) * 8;

                    float acc[4][8][4];
#pragma unroll
                    for (int mf = 0; mf < 4; mf++)
#pragma unroll
                        for (int nf = 0; nf < 8; nf++)
#pragma unroll
                            for (int c = 0; c < 4; c++) acc[mf][nf][c] = 0.f;

                    const int KIT = D_DIM / BK;  // 8
                    auto load_stage = [&](int kt) {
                        const int s = kt % STAGES;
                        const __half* ap = aptr + kt * BK;
                        const __half* bp = bptr + (size_t)kt * BK * F_DIM;
#pragma unroll
                        for (int i = 0; i < 8; i++)
                            cp16(uA[s] + sa_o + i * (16 * A_ROW_B), ap + (size_t)i * 16 * D_DIM);
#pragma unroll
                        for (int i = 0; i < 8; i++)
                            cp16(uB[s] + sb_o + i * (8 * B_ROW_B), bp + (size_t)i * 8 * F_DIM);
                        CP_COMMIT();
                    };
                    load_stage(0);
                    load_stage(1);
                    for (int kt = 0; kt < KIT; kt++) {
                        if (kt + 1 < KIT) { asm volatile("cp.async.wait_group 1;"); }
                        else              { asm volatile("cp.async.wait_group 0;"); }
                        __syncthreads();
                        if (kt + 2 < KIT) load_stage(kt + 2);
                        const uint32_t ua = uA[kt % STAGES];
                        const uint32_t ub = uB[kt % STAGES];
#pragma unroll
                        for (int c = 0; c < 4; c++) {
                            uint32_t a[4][4];
#pragma unroll
                            for (int mf = 0; mf < 4; mf++) {
                                int row = wm + mf * 16 + (lane & 7) + ((lane >> 3) & 1) * 8;
                                LDSM_X4(a[mf], ua + row * A_ROW_B + c * 32 + (lane >> 4) * 16);
                            }
                            uint32_t bfr[8][2];
#pragma unroll
                            for (int p = 0; p < 4; p++) {
                                int k = c * 16 + ((lane >> 3) & 1) * 8 + (lane & 7);
                                int n = wn + p * 16 + (lane >> 4) * 8;
                                uint32_t r0, r1, r2, r3;
                                LDSM_X4_T(r0, r1, r2, r3, ub + k * B_ROW_B + n * 2);
                                bfr[2 * p][0] = r0; bfr[2 * p][1] = r1;
                                bfr[2 * p + 1][0] = r2; bfr[2 * p + 1][1] = r3;
                            }
#pragma unroll
                            for (int mf = 0; mf < 4; mf++)
#pragma unroll
                                for (int nf = 0; nf < 8; nf++)
                                    mma_f16(acc[mf][nf], a[mf], bfr[nf]);
                        }
                    }
                    // epilogue: bias + gelu -> fp16 H
                    const int g = lane >> 2, t2 = lane & 3;
#pragma unroll
                    for (int mf = 0; mf < 4; mf++) {
#pragma unroll
                        for (int nf = 0; nf < 8; nf++) {
                            int row0 = wm + mf * 16 + g;
                            int colL = wn + nf * 8 + t2 * 2;
                            float b0 = sbias[colL], b1v = sbias[colL + 1];
                            int lr = tm + row0;
                            if (lr < ne) {
                                uint32_t h = pack_h2(gelu_exact(acc[mf][nf][0] + b0),
                                                     gelu_exact(acc[mf][nf][1] + b1v));
                                *reinterpret_cast<uint32_t*>(
                                    &g_Hh[(size_t)(base + lr) * F_DIM + n0 + colL]) = h;
                            }
                            if (lr + 8 < ne) {
                                uint32_t h = pack_h2(gelu_exact(acc[mf][nf][2] + b0),
                                                     gelu_exact(acc[mf][nf][3] + b1v));
                                *reinterpret_cast<uint32_t*>(
                                    &g_Hh[(size_t)(base + lr + 8) * F_DIM + n0 + colL]) = h;
                            }
                        }
                    }
                }
                __threadfence();
                __syncthreads();
                if (tid == 0) atomicAdd(&g_flag1[e], 1);
            }
        } else {
            // ---- gemm2 item: out = Hh @ W2h + b2, scattered ----
            const int g2 = (int)(idx - N_PH1);
            const int x = g2 & 3, y = (g2 >> 2) & 7, e = g2 >> 5;
            const int base = g_offsets[e];
            const int ne   = g_offsets[e + 1] - base;
            const int tm   = y * BM;
            if (tm < ne) {
                if (tid == 0) {
                    while (((volatile int*)g_flag1)[e] < 128 ||
                           ((volatile int*)g_cflag)[e] < 16)
                        __nanosleep(64);
                }
                __syncthreads();
                __threadfence();

                const int n0 = x * BN;
                stoks[tid] = (tm + tid < ne) ? g_tok[base + tm + tid] : -1;
                sbias[tid] = B2g[e * D_DIM + n0 + tid];
                __syncthreads();

                const __half* aptr = g_Hh + ((size_t)(base + tm) + (tid >> 3)) * F_DIM + (tid & 7) * 8;
                const __half* bptr = g_W2h + ((size_t)e * F_DIM + (tid >> 4)) * D_DIM + n0 + (tid & 15) * 8;

                float acc[4][8][4];
#pragma unroll
                for (int mf = 0; mf < 4; mf++)
#pragma unroll
                    for (int nf = 0; nf < 8; nf++)
#pragma unroll
                        for (int c = 0; c < 4; c++) acc[mf][nf][c] = 0.f;

                const int KIT = F_DIM / BK;  // 32
                auto load_stage = [&](int kt) {
                    const int s = kt % STAGES;
                    const __half* ap = aptr + kt * BK;
                    const __half* bp = bptr + (size_t)kt * BK * D_DIM;
#pragma unroll
                    for (int i = 0; i < 8; i++)
                        cp16(uA[s] + sa_o + i * (16 * A_ROW_B), ap + (size_t)i * 16 * F_DIM);
#pragma unroll
                    for (int i = 0; i < 8; i++)
                        cp16(uB[s] + sb_o + i * (8 * B_ROW_B), bp + (size_t)i * 8 * D_DIM);
                    CP_COMMIT();
                };
                load_stage(0);
                load_stage(1);
                for (int kt = 0; kt < KIT; kt++) {
                    if (kt + 1 < KIT) { asm volatile("cp.async.wait_group 1;"); }
                    else              { asm volatile("cp.async.wait_group 0;"); }
                    __syncthreads();
                    if (kt + 2 < KIT) load_stage(kt + 2);
                    const uint32_t ua = uA[kt % STAGES];
                    const uint32_t ub = uB[kt % STAGES];
#pragma unroll
                    for (int c = 0; c < 4; c++) {
                        uint32_t a[4][4];
#pragma unroll
                        for (int mf = 0; mf < 4; mf++) {
                            int row = wm + mf * 16 + (lane & 7) + ((lane >> 3) & 1) * 8;
                            LDSM_X4(a[mf], ua + row * A_ROW_B + c * 32 + (lane >> 4) * 16);
                        }
                        uint32_t bfr[8][2];
#pragma unroll
                        for (int p = 0; p < 4; p++) {
                            int k = c * 16 + ((lane >> 3) & 1) * 8 + (lane & 7);
                            int n = wn + p * 16 + (lane >> 4) * 8;
                            uint32_t r0, r1, r2, r3;
                            LDSM_X4_T(r0, r1, r2, r3, ub + k * B_ROW_B + n * 2);
                            bfr[2 * p][0] = r0; bfr[2 * p][1] = r1;
                            bfr[2 * p + 1][0] = r2; bfr[2 * p + 1][1] = r3;
                        }
#pragma unroll
                        for (int mf = 0; mf < 4; mf++)
#pragma unroll
                            for (int nf = 0; nf < 8; nf++)
                                mma_f16(acc[mf][nf], a[mf], bfr[nf]);
                    }
                }
                // epilogue: bias + scatter fp32
                const int g = lane >> 2, t2 = lane & 3;
#pragma unroll
                for (int mf = 0; mf < 4; mf++) {
#pragma unroll
                    for (int nf = 0; nf < 8; nf++) {
                        int row0 = wm + mf * 16 + g;
                        int colL = wn + nf * 8 + t2 * 2;
                        float b0 = sbias[colL], b1v = sbias[colL + 1];
                        int lr = tm + row0;
                        if (lr < ne) {
                            int tok = stoks[row0];
                            float2 o = make_float2(acc[mf][nf][0] + b0, acc[mf][nf][1] + b1v);
                            *reinterpret_cast<float2*>(&out[(size_t)tok * D_DIM + n0 + colL]) = o;
                        }
                        if (lr + 8 < ne) {
                            int tok = stoks[row0 + 8];
                            float2 o = make_float2(acc[mf][nf][2] + b0, acc[mf][nf][3] + b1v);
                            *reinterpret_cast<float2*>(&out[(size_t)tok * D_DIM + n0 + colL]) = o;
                        }
                    }
                }
            }
        }
    }
}

// ---------------- launch ----------------
extern "C" void kernel_launch(void* const* d_in, const int* in_sizes, int n_in,
                              void* d_out, int out_size)
{
    const float* X    = (const float*)d_in[0];
    const int*   disp = (const int*)d_in[1];
    const float* W1   = (const float*)d_in[2];
    const float* B1   = (const float*)d_in[3];
    const float* W2   = (const float*)d_in[4];
    const float* B2   = (const float*)d_in[5];
    float*       out  = (float*)d_out;

    cudaFuncSetAttribute(moe_kernel, cudaFuncAttributeMaxDynamicSharedMemorySize, DSMEM_B);

    prep_kernel<<<1 + WELEMS / (1024 * 8), 1024>>>(disp, W1);   // dispatch ∥ W1 convert
    gather_x_kernel<<<T_TOKENS / 2, 256>>>(X);
    moe_kernel<<<304, NTH, DSMEM_B>>>(W2, B1, B2, out);          // persistent fused
}